// round 14
// baseline (speedup 1.0000x reference)
#include <cuda_runtime.h>
#include <cstdint>
#include <math.h>

#define BB   256
#define SS   4096
#define VV   6
#define DD   32
#define HH   16
#define PADV 5
#define KK   614          // max(1, int(4096*0.15))
#define CL   2            // chunks per row
#define TOKC (SS / CL)    // 2048 tokens per chunk
#define TPB  256
#define NW   (TPB / 32)   // 8 warps
#define FULL 0xffffffffu

// Cross-kernel scratch
__device__ int   g_counts[BB][CL][VV];
__device__ float g_sscore[VV];
__device__ float g_arow[VV][DD];
__device__ int   g_order[VV];

// spread 3x10-bit u32 fields into 3x21-bit u64 fields
__device__ __forceinline__ unsigned long long sp21(unsigned int a) {
    return (unsigned long long)(a & 1023u)
         | ((unsigned long long)((a >> 10) & 1023u) << 21)
         | ((unsigned long long)((a >> 20) & 1023u) << 42);
}

// ---------------- K1: per-chunk vocab counts + one MLP CTA ----------------
__global__ __launch_bounds__(TPB, 8) void count_kernel(
    const int*   __restrict__ x,
    const float* __restrict__ emb,
    const float* __restrict__ sw1, const float* __restrict__ sb1,
    const float* __restrict__ sw2, const float* __restrict__ sb2,
    const float* __restrict__ aw1, const float* __restrict__ ab1,
    const float* __restrict__ aw2, const float* __restrict__ ab2)
{
    const int t = threadIdx.x;

    // PDL: dependent grid may begin; its wait still blocks until K1 completes.
    asm volatile("griddepcontrol.launch_dependents;" ::: "memory");

    if (blockIdx.x < BB * CL) {
        // one CTA per chunk: 2048 tokens, 8 per thread
        const int b = blockIdx.x >> 1;
        const int c = blockIdx.x & 1;
        const int4* p = (const int4*)(x + (size_t)b * SS + c * TOKC + t * 8);
        const int4 w0 = p[0], w1 = p[1];

        unsigned long long h =
            (1ull << (10 * w0.x)) + (1ull << (10 * w0.y)) +
            (1ull << (10 * w0.z)) + (1ull << (10 * w0.w)) +
            (1ull << (10 * w1.x)) + (1ull << (10 * w1.y)) +
            (1ull << (10 * w1.z)) + (1ull << (10 * w1.w));
        #pragma unroll
        for (int off = 16; off > 0; off >>= 1)
            h += __shfl_xor_sync(FULL, h, off);

        __shared__ unsigned long long wtot[NW];
        if ((t & 31) == 0) wtot[t >> 5] = h;
        __syncthreads();
        if (t < VV) {
            int s = 0;
            #pragma unroll
            for (int w = 0; w < NW; ++w) s += (int)((wtot[w] >> (10 * t)) & 1023ull);
            g_counts[b][c][t] = s;
        }
        return;
    }

    // ---- single MLP CTA (row-independent tables) ----
    __shared__ float table[VV][DD];
    __shared__ float rbuf[VV][DD];
    __shared__ float hbuf[VV][HH];
    __shared__ float ssc[VV];

    if (t < VV * DD) {
        int v = t >> 5, i = t & 31;
        table[v][i] = (v == PADV) ? 0.0f : emb[v * DD + i];
    }
    __syncthreads();
    if (t < VV * DD) {
        int v = t >> 5, i = t & 31;
        float acc = ab1[i];
        #pragma unroll
        for (int d = 0; d < DD; ++d) acc += table[v][d] * aw1[d * DD + i];
        rbuf[v][i] = fmaxf(acc, 0.0f);
    }
    if (t < VV * HH) {
        int v = t >> 4, j = t & 15;
        float acc = sb1[j];
        #pragma unroll
        for (int d = 0; d < DD; ++d) acc += table[v][d] * sw1[d * HH + j];
        hbuf[v][j] = fmaxf(acc, 0.0f);
    }
    __syncthreads();
    if (t < VV * DD) {
        int v = t >> 5, i = t & 31;
        float acc = ab2[i];
        #pragma unroll
        for (int m = 0; m < DD; ++m) acc += rbuf[v][m] * aw2[m * DD + i];
        g_arow[v][i] = acc;
    }
    if (t >= 224 && t < 224 + VV) {
        int v = t - 224;
        float acc = sb2[0];
        #pragma unroll
        for (int j = 0; j < HH; ++j) acc += hbuf[v][j] * sw2[j];
        float s = 1.0f / (1.0f + expf(-acc));
        ssc[v] = s;
        g_sscore[v] = s;
    }
    __syncthreads();
    if (t == 0) {
        int order[VV];
        #pragma unroll
        for (int v = 0; v < VV; ++v) order[v] = v;
        for (int a = 0; a < VV; ++a) {
            int best = a;
            for (int q = a + 1; q < VV; ++q)
                if (ssc[order[q]] > ssc[order[best]]) best = q;
            int tmp = order[a]; order[a] = order[best]; order[best] = tmp;
        }
        #pragma unroll
        for (int a = 0; a < VV; ++a) g_order[a] = order[a];
    }
}

// ---------------- K2: scores + top_idx + pred (PDL consumer) ----------------
__global__ __launch_bounds__(TPB, 4) void emit_kernel(
    const int*   __restrict__ x,
    const float* __restrict__ cw1, const float* __restrict__ cb1,
    const float* __restrict__ cw2, const float* __restrict__ cb2,
    float* __restrict__ out_pred,
    float* __restrict__ out_top,
    float* __restrict__ out_sc)
{
    __shared__ unsigned int wA[NW], wB[NW];              // per-warp inclusive totals
    __shared__ unsigned long long exA[NW], exB[NW];      // cross-warp excl (21-bit)
    __shared__ unsigned long long tp_sh, op_sh;          // take/obase (10-bit)
    __shared__ unsigned long long cpA_sh, cpB_sh;        // chunk prefix (21-bit)

    const int t    = threadIdx.x;
    const int lane = t & 31;
    const int warp = t >> 5;
    const int b    = blockIdx.x >> 1;
    const int c    = blockIdx.x & 1;

    // ---------- K1-independent prologue ----------
    const int4* p = (const int4*)(x + (size_t)b * SS + c * TOKC + t * 8);
    const int4 x0 = p[0], x1 = p[1];

    unsigned long long h =
        (1ull << (10 * x0.x)) + (1ull << (10 * x0.y)) +
        (1ull << (10 * x0.z)) + (1ull << (10 * x0.w)) +
        (1ull << (10 * x1.x)) + (1ull << (10 * x1.y)) +
        (1ull << (10 * x1.z)) + (1ull << (10 * x1.w));
    const unsigned int hA = (unsigned int)(h & 0x3FFFFFFFull);   // v0..2, 10-bit
    const unsigned int hB = (unsigned int)(h >> 30);             // v3..5, 10-bit

    unsigned int sA = hA, sB = hB;                        // inclusive warp scans
    #pragma unroll
    for (int off = 1; off < 32; off <<= 1) {
        unsigned int nA = __shfl_up_sync(FULL, sA, off);
        unsigned int nB = __shfl_up_sync(FULL, sB, off);
        if (lane >= off) { sA += nA; sB += nB; }
    }
    if (lane == 31) { wA[warp] = sA; wB[warp] = sB; }
    __syncthreads();                                           // S1

    // cross-warp exclusive prefixes in 21-bit domain (redundant-parallel, t<NW)
    if (t < NW) {
        unsigned long long a = 0ull, bb2 = 0ull;
        #pragma unroll
        for (int w = 0; w < NW; ++w)
            if (w < t) { a += sp21(wA[w]); bb2 += sp21(wB[w]); }
        exA[t] = a; exB[t] = bb2;
    }

    // ---------- wait for K1 (counts, scores, order, arow) ----------
    asm volatile("griddepcontrol.wait;" ::: "memory");

    const float ms = (lane < VV) ? g_sscore[lane] : 0.0f;   // per-warp score regs

    if (t == 0) {
        // static-indexed budget computation (no local memory)
        int c0[VV], c1[VV], rt[VV];
        #pragma unroll
        for (int v = 0; v < VV; ++v) {
            c0[v] = g_counts[b][0][v];
            c1[v] = g_counts[b][1][v];
            rt[v] = c0[v] + c1[v];
        }
        float sc[VV];
        #pragma unroll
        for (int v = 0; v < VV; ++v) sc[v] = g_sscore[v];
        int rnk[VV];
        #pragma unroll
        for (int v = 0; v < VV; ++v) {
            int r = 0;
            #pragma unroll
            for (int u = 0; u < VV; ++u)
                r += (sc[u] > sc[v]) || (sc[u] == sc[v] && u < v);
            rnk[v] = r;
        }
        unsigned long long tp = 0ull, op = 0ull;
        int budget = KK, off = 0;
        #pragma unroll
        for (int r = 0; r < VV; ++r) {
            int vsel = 0, tot = 0;
            #pragma unroll
            for (int v = 0; v < VV; ++v)
                if (rnk[v] == r) { vsel = v; tot = rt[v]; }
            int tk = min(tot, budget);
            tp |= (unsigned long long)tk  << (10 * vsel);
            op |= (unsigned long long)off << (10 * vsel);
            off    += tk;
            budget -= tk;
        }
        tp_sh = tp; op_sh = op;
        // chunk prefix: tokens of vocab v in chunks before c
        if (c) {
            cpA_sh = (unsigned long long)c0[0] |
                     ((unsigned long long)c0[1] << 21) |
                     ((unsigned long long)c0[2] << 42);
            cpB_sh = (unsigned long long)c0[3] |
                     ((unsigned long long)c0[4] << 21) |
                     ((unsigned long long)c0[5] << 42);
        } else {
            cpA_sh = 0ull; cpB_sh = 0ull;
        }
    }
    __syncthreads();                                           // S2

    // ---------- scores output: shfl-select, 2x float4 ----------
    {
        float4 f0, f1;
        f0.x = __shfl_sync(FULL, ms, x0.x);
        f0.y = __shfl_sync(FULL, ms, x0.y);
        f0.z = __shfl_sync(FULL, ms, x0.z);
        f0.w = __shfl_sync(FULL, ms, x0.w);
        f1.x = __shfl_sync(FULL, ms, x1.x);
        f1.y = __shfl_sync(FULL, ms, x1.y);
        f1.z = __shfl_sync(FULL, ms, x1.z);
        f1.w = __shfl_sync(FULL, ms, x1.w);
        float4* sp = (float4*)(out_sc + (size_t)b * SS + c * TOKC);
        sp[2 * t]     = f0;
        sp[2 * t + 1] = f1;
    }

    // ---------- top_idx emit: register-packed 21-bit ordinals ----------
    {
        unsigned long long pA = cpA_sh + exA[warp] + sp21(sA - hA);
        unsigned long long pB = cpB_sh + exB[warp] + sp21(sB - hB);
        const unsigned long long tp = tp_sh, op = op_sh;
        float* trow = out_top + (size_t)b * KK;
        const int pbase = c * TOKC + t * 8;
        const int tok[8] = {x0.x, x0.y, x0.z, x0.w, x1.x, x1.y, x1.z, x1.w};
        #pragma unroll
        for (int j = 0; j < 8; ++j) {
            const int  v    = tok[j];
            const bool hi   = v >= 3;
            const int  sh21 = (hi ? v - 3 : v) * 21;
            const unsigned long long cur = hi ? pB : pA;
            const int  ord  = (int)((cur >> sh21) & 0x1FFFFFull);
            const unsigned long long inc = 1ull << sh21;
            if (hi) pB += inc; else pA += inc;
            const int sh10 = v * 10;
            const int tk = (int)((tp >> sh10) & 1023ull);
            const int ob = (int)((op >> sh10) & 1023ull);
            if (ord < tk)
                trow[ob + ord] = (float)(pbase + j);
        }
    }

    // ---------- classifier: warp 0 of chunk-0 CTA, shuffle-only ----------
    if (c == 0 && warp == 0) {
        const unsigned long long tp = tp_sh;
        float pooled = 0.0f;
        #pragma unroll
        for (int v = 0; v < VV; ++v)
            pooled += (float)((int)((tp >> (10 * v)) & 1023ull)) * g_arow[v][lane];
        pooled *= (1.0f / (float)KK);

        float hh = (lane < HH) ? cb1[lane] : 0.0f;
        #pragma unroll
        for (int d = 0; d < DD; ++d) {
            const float pv = __shfl_sync(FULL, pooled, d);
            if (lane < HH) hh += pv * cw1[d * HH + lane];
        }
        hh = fmaxf(hh, 0.0f);
        float contrib = (lane < HH) ? hh * cw2[lane] : 0.0f;
        #pragma unroll
        for (int off = 16; off > 0; off >>= 1)
            contrib += __shfl_xor_sync(FULL, contrib, off);
        if (lane == 0)
            out_pred[b] = 1.0f / (1.0f + expf(-(contrib + cb2[0])));
    }
}

extern "C" void kernel_launch(void* const* d_in, const int* in_sizes, int n_in,
                              void* d_out, int out_size) {
    const int*   x   = (const int*)  d_in[0];
    const float* emb = (const float*)d_in[1];
    const float* sw1 = (const float*)d_in[2];
    const float* sb1 = (const float*)d_in[3];
    const float* sw2 = (const float*)d_in[4];
    const float* sb2 = (const float*)d_in[5];
    const float* aw1 = (const float*)d_in[6];
    const float* ab1 = (const float*)d_in[7];
    const float* aw2 = (const float*)d_in[8];
    const float* ab2 = (const float*)d_in[9];
    const float* cw1 = (const float*)d_in[10];
    const float* cb1 = (const float*)d_in[11];
    const float* cw2 = (const float*)d_in[12];
    const float* cb2 = (const float*)d_in[13];

    float* out      = (float*)d_out;
    float* out_pred = out;
    float* out_top  = out + BB;
    float* out_sc   = out + BB + (size_t)BB * KK;

    count_kernel<<<BB * CL + 1, TPB>>>(x, emb, sw1, sb1, sw2, sb2,
                                       aw1, ab1, aw2, ab2);

    cudaLaunchConfig_t cfg = {};
    cfg.gridDim  = dim3(BB * CL);
    cfg.blockDim = dim3(TPB);
    cfg.dynamicSmemBytes = 0;
    cfg.stream   = 0;
    cudaLaunchAttribute attrs[1];
    attrs[0].id = cudaLaunchAttributeProgrammaticStreamSerialization;
    attrs[0].val.programmaticStreamSerializationAllowed = 1;
    cfg.attrs    = attrs;
    cfg.numAttrs = 1;
    cudaLaunchKernelEx(&cfg, emit_kernel, x, cw1, cb1, cw2, cb2,
                       out_pred, out_top, out_sc);
}

// round 16
// speedup vs baseline: 1.0751x; 1.0751x over previous
#include <cuda_runtime.h>
#include <cstdint>
#include <math.h>

#define BB   256
#define SS   4096
#define VV   6
#define DD   32
#define HH   16
#define PADV 5
#define KK   614          // max(1, int(4096*0.15))
#define CL   2            // CTAs per row
#define TOKC (SS / CL)    // 2048 tokens per CTA
#define TPB  256
#define NW   (TPB / 32)   // 8 warps
#define FULL 0xffffffffu

// Inter-CTA scratch. g_flag uses parity toggling -> no reset needed across
// graph replays (each kernel execution toggles each bit exactly once).
__device__ int          g_counts[BB][CL][VV];
__device__ unsigned int g_flag[BB];

// spread 3x10-bit u32 fields into 3x21-bit u64 fields
__device__ __forceinline__ unsigned long long sp21(unsigned int a) {
    return (unsigned long long)(a & 1023u)
         | ((unsigned long long)((a >> 10) & 1023u) << 21)
         | ((unsigned long long)((a >> 20) & 1023u) << 42);
}

__global__ __launch_bounds__(TPB, 4) void fused_kernel(
    const int*   __restrict__ x,
    const float* __restrict__ emb,
    const float* __restrict__ sw1, const float* __restrict__ sb1,
    const float* __restrict__ sw2, const float* __restrict__ sb2,
    const float* __restrict__ aw1, const float* __restrict__ ab1,
    const float* __restrict__ aw2, const float* __restrict__ ab2,
    const float* __restrict__ cw1, const float* __restrict__ cb1,
    const float* __restrict__ cw2, const float* __restrict__ cb2,
    float* __restrict__ out_pred,
    float* __restrict__ out_top,
    float* __restrict__ out_sc)
{
    __shared__ float table[VV][DD];
    __shared__ float rbuf[VV][DD];
    __shared__ float hbuf[VV][HH];
    __shared__ float arow[VV][DD];
    __shared__ float sscore[VV];
    __shared__ unsigned int wA[NW], wB[NW];            // per-warp inclusive totals
    __shared__ unsigned long long exA[NW], exB[NW];    // cross-warp excl (21-bit)
    __shared__ unsigned long long tp_sh, op_sh;        // take/obase packs (10-bit)
    __shared__ unsigned long long cpA_sh, cpB_sh;      // sibling-chunk prefix (21-bit)

    const int t    = threadIdx.x;
    const int lane = t & 31;
    const int warp = t >> 5;
    const int b    = blockIdx.x >> 1;
    const int c    = blockIdx.x & 1;

    // ---- issue x loads early: 8 contiguous tokens per thread ----
    const int4* p = (const int4*)(x + (size_t)b * SS + c * TOKC + t * 8);
    const int4 x0 = p[0], x1 = p[1];

    // ---- MLP stage 1: table = emb with PAD row zeroed ----
    if (t < VV * DD) {
        int v = t >> 5, i = t & 31;
        table[v][i] = (v == PADV) ? 0.0f : emb[v * DD + i];
    }
    __syncthreads();                                           // S1

    // ---- MLP hidden layers ----
    if (t < VV * DD) {
        int v = t >> 5, i = t & 31;
        float acc = ab1[i];
        #pragma unroll
        for (int d = 0; d < DD; ++d) acc += table[v][d] * aw1[d * DD + i];
        rbuf[v][i] = fmaxf(acc, 0.0f);
    }
    if (t < VV * HH) {
        int v = t >> 4, j = t & 15;
        float acc = sb1[j];
        #pragma unroll
        for (int d = 0; d < DD; ++d) acc += table[v][d] * sw1[d * HH + j];
        hbuf[v][j] = fmaxf(acc, 0.0f);
    }

    // ---- counting: packed 6x10-bit, split into two u32 scans (overlaps MLP) ----
    unsigned long long h =
        (1ull << (10 * x0.x)) + (1ull << (10 * x0.y)) +
        (1ull << (10 * x0.z)) + (1ull << (10 * x0.w)) +
        (1ull << (10 * x1.x)) + (1ull << (10 * x1.y)) +
        (1ull << (10 * x1.z)) + (1ull << (10 * x1.w));
    const unsigned int hA = (unsigned int)(h & 0x3FFFFFFFull);   // v0..2
    const unsigned int hB = (unsigned int)(h >> 30);             // v3..5

    unsigned int sA = hA, sB = hB;                        // inclusive warp scans
    #pragma unroll
    for (int off = 1; off < 32; off <<= 1) {
        unsigned int nA = __shfl_up_sync(FULL, sA, off);
        unsigned int nB = __shfl_up_sync(FULL, sB, off);
        if (lane >= off) { sA += nA; sB += nB; }
    }
    if (lane == 31) { wA[warp] = sA; wB[warp] = sB; }
    __syncthreads();                                           // S2

    // ---- MLP output layers ----
    if (t < VV * DD) {
        int v = t >> 5, i = t & 31;
        float acc = ab2[i];
        #pragma unroll
        for (int m = 0; m < DD; ++m) acc += rbuf[v][m] * aw2[m * DD + i];
        arow[v][i] = acc;
    }
    if (t >= 224 && t < 224 + VV) {
        int v = t - 224;
        float acc = sb2[0];
        #pragma unroll
        for (int j = 0; j < HH; ++j) acc += hbuf[v][j] * sw2[j];
        sscore[v] = 1.0f / (1.0f + expf(-acc));
    }
    // cross-warp exclusive prefixes (21-bit domain)
    if (t >= 32 && t < 32 + NW) {
        const int w0 = t - 32;
        unsigned long long a = 0ull, bb = 0ull;
        #pragma unroll
        for (int w = 0; w < NW; ++w)
            if (w < w0) { a += sp21(wA[w]); bb += sp21(wB[w]); }
        exA[w0] = a; exB[w0] = bb;
    }
    // this CTA's per-vocab totals -> global (plain stores land in L2)
    if (t < VV) {
        int cnt;
        if (t < 3) {
            unsigned int tot = wA[0];
            #pragma unroll
            for (int w = 1; w < NW; ++w) tot += wA[w];
            cnt = (int)((tot >> (10 * t)) & 1023u);
        } else {
            unsigned int tot = wB[0];
            #pragma unroll
            for (int w = 1; w < NW; ++w) tot += wB[w];
            cnt = (int)((tot >> (10 * (t - 3))) & 1023u);
        }
        g_counts[b][c][t] = cnt;
    }
    __syncthreads();                                           // S3

    // ---- thread 0: handshake with sibling CTA + budget math.
    //      All other threads overlap this with the scores store. ----
    if (t == 0) {
        __threadfence();                                   // counts visible (release)
        const unsigned int old = atomicXor(&g_flag[b], 1u << c);
        const unsigned int target = (((old >> c) & 1u) ^ 1u) ? 0x3u : 0x0u;
        while ((atomicAdd(&g_flag[b], 0u) & 0x3u) != target) { }
        __threadfence();                                   // acquire

        int c0[VV], c1[VV];
        #pragma unroll
        for (int v = 0; v < VV; ++v) {
            c0[v] = __ldcg(&g_counts[b][0][v]);
            c1[v] = __ldcg(&g_counts[b][1][v]);
        }
        float sc[VV];
        #pragma unroll
        for (int v = 0; v < VV; ++v) sc[v] = sscore[v];
        int rnk[VV];                                       // static pairwise rank
        #pragma unroll
        for (int v = 0; v < VV; ++v) {
            int r = 0;
            #pragma unroll
            for (int u = 0; u < VV; ++u)
                r += (sc[u] > sc[v]) || (sc[u] == sc[v] && u < v);
            rnk[v] = r;
        }
        unsigned long long tp = 0ull, op = 0ull;
        int budget = KK, off = 0;
        #pragma unroll
        for (int r = 0; r < VV; ++r) {
            int vsel = 0, tot = 0;
            #pragma unroll
            for (int v = 0; v < VV; ++v)
                if (rnk[v] == r) { vsel = v; tot = c0[v] + c1[v]; }
            int tk = min(tot, budget);
            tp |= (unsigned long long)tk  << (10 * vsel);
            op |= (unsigned long long)off << (10 * vsel);
            off    += tk;
            budget -= tk;
        }
        tp_sh = tp; op_sh = op;
        if (c) {
            cpA_sh = (unsigned long long)c0[0] |
                     ((unsigned long long)c0[1] << 21) |
                     ((unsigned long long)c0[2] << 42);
            cpB_sh = (unsigned long long)c0[3] |
                     ((unsigned long long)c0[4] << 21) |
                     ((unsigned long long)c0[5] << 42);
        } else {
            cpA_sh = 0ull; cpB_sh = 0ull;
        }
    }

    // ---- scores output (overlaps thread 0's spin): shfl-select ----
    {
        const float ms = (lane < VV) ? sscore[lane] : 0.0f;
        float4 f0, f1;
        f0.x = __shfl_sync(FULL, ms, x0.x);
        f0.y = __shfl_sync(FULL, ms, x0.y);
        f0.z = __shfl_sync(FULL, ms, x0.z);
        f0.w = __shfl_sync(FULL, ms, x0.w);
        f1.x = __shfl_sync(FULL, ms, x1.x);
        f1.y = __shfl_sync(FULL, ms, x1.y);
        f1.z = __shfl_sync(FULL, ms, x1.z);
        f1.w = __shfl_sync(FULL, ms, x1.w);
        float4* sp = (float4*)(out_sc + (size_t)b * SS + c * TOKC);
        sp[2 * t]     = f0;
        sp[2 * t + 1] = f1;
    }
    __syncthreads();                                           // S4

    // ---- top_idx emit: register-packed 21-bit ordinals ----
    {
        unsigned long long pA = cpA_sh + exA[warp] + sp21(sA - hA);
        unsigned long long pB = cpB_sh + exB[warp] + sp21(sB - hB);
        const unsigned long long tp = tp_sh, op = op_sh;
        float* trow = out_top + (size_t)b * KK;
        const int pbase = c * TOKC + t * 8;
        const int tok[8] = {x0.x, x0.y, x0.z, x0.w, x1.x, x1.y, x1.z, x1.w};
        #pragma unroll
        for (int j = 0; j < 8; ++j) {
            const int  v    = tok[j];
            const bool hi   = v >= 3;
            const int  sh21 = (hi ? v - 3 : v) * 21;
            const unsigned long long cur = hi ? pB : pA;
            const int  ord  = (int)((cur >> sh21) & 0x1FFFFFull);
            const unsigned long long inc = 1ull << sh21;
            if (hi) pB += inc; else pA += inc;
            const int sh10 = v * 10;
            const int tk = (int)((tp >> sh10) & 1023ull);
            const int ob = (int)((op >> sh10) & 1023ull);
            if (ord < tk)
                trow[ob + ord] = (float)(pbase + j);
        }
    }

    // ---- classifier: warp 0 of chunk-0 CTA, shuffle-only ----
    if (c == 0 && warp == 0) {
        const unsigned long long tp = tp_sh;
        float pooled = 0.0f;
        #pragma unroll
        for (int v = 0; v < VV; ++v)
            pooled += (float)((int)((tp >> (10 * v)) & 1023ull)) * arow[v][lane];
        pooled *= (1.0f / (float)KK);

        float hh = (lane < HH) ? cb1[lane] : 0.0f;
        #pragma unroll
        for (int d = 0; d < DD; ++d) {
            const float pv = __shfl_sync(FULL, pooled, d);
            if (lane < HH) hh += pv * cw1[d * HH + lane];
        }
        hh = fmaxf(hh, 0.0f);
        float contrib = (lane < HH) ? hh * cw2[lane] : 0.0f;
        #pragma unroll
        for (int off = 16; off > 0; off >>= 1)
            contrib += __shfl_xor_sync(FULL, contrib, off);
        if (lane == 0)
            out_pred[b] = 1.0f / (1.0f + expf(-(contrib + cb2[0])));
    }
}

extern "C" void kernel_launch(void* const* d_in, const int* in_sizes, int n_in,
                              void* d_out, int out_size) {
    const int*   x   = (const int*)  d_in[0];
    const float* emb = (const float*)d_in[1];
    const float* sw1 = (const float*)d_in[2];
    const float* sb1 = (const float*)d_in[3];
    const float* sw2 = (const float*)d_in[4];
    const float* sb2 = (const float*)d_in[5];
    const float* aw1 = (const float*)d_in[6];
    const float* ab1 = (const float*)d_in[7];
    const float* aw2 = (const float*)d_in[8];
    const float* ab2 = (const float*)d_in[9];
    const float* cw1 = (const float*)d_in[10];
    const float* cb1 = (const float*)d_in[11];
    const float* cw2 = (const float*)d_in[12];
    const float* cb2 = (const float*)d_in[13];

    float* out      = (float*)d_out;
    float* out_pred = out;
    float* out_top  = out + BB;
    float* out_sc   = out + BB + (size_t)BB * KK;

    // grid = 512 CTAs; __launch_bounds__(256,4) guarantees >=4 CTAs/SM
    // (592 resident slots on 148 SMs), so all CTAs are co-resident in wave 1
    // and the per-row flag handshake cannot deadlock.
    fused_kernel<<<BB * CL, TPB>>>(x, emb, sw1, sb1, sw2, sb2,
                                   aw1, ab1, aw2, ab2,
                                   cw1, cb1, cw2, cb2,
                                   out_pred, out_top, out_sc);
}